// round 16
// baseline (speedup 1.0000x reference)
#include <cuda_runtime.h>
#include <cuda_fp16.h>
#include <math.h>

#define NN 100000
#define EE 3200000
#define FF 128
#define HH 16
#define CC 40
#define ALPHA 0.1f
#define BN_EPS 1e-5f
#define SB 512                 // scan block size

// ---------------- scratch (device globals; no allocation) ----------------
__device__ __align__(16) __half g_tmps[NN * HH];  // fp16 x@W1 (raw, then *dinv in scan1)
__device__ __align__(16) __half g_h2s[NN * HH];   // fp16 post-hops hidden * dinv (src-side)
__device__ __align__(16) float g_h[NN * HH];      // fp32 post-relu hidden
__device__ float g_dinv[NN];
__device__ float g_stats[2 * HH];
// CSR machinery
__device__ int g_cnt[NN];          // in-degree (no self loop) -- zeroed by memset node
__device__ int g_off[NN];          // CSR row start (block-LOCAL; add g_bpre[node/SB])
__device__ int g_btot[256];        // scan block totals
__device__ int g_bpre[256];        // scan block prefixes
__device__ int g_flag = 0;         // last-block counter for scan1 (self-resetting)
__device__ int g_rank[EE];         // per-edge rank within its dst row
__device__ int g_csr[EE];          // src indices grouped by dst

// ---------------- helpers ----------------
__device__ __forceinline__ float4 h8_to_f4(uint2 a) {
    __half2 h0 = *reinterpret_cast<__half2*>(&a.x);
    __half2 h1 = *reinterpret_cast<__half2*>(&a.y);
    float2 f0 = __half22float2(h0);
    float2 f1 = __half22float2(h1);
    return make_float4(f0.x, f0.y, f1.x, f1.y);
}
__device__ __forceinline__ void acc4(float4& a, float4 v) {
    a.x += v.x; a.y += v.y; a.z += v.z; a.w += v.w;
}
__device__ __forceinline__ unsigned pack_h2(float a, float b) {
    __half2 p = __floats2half2_rn(a, b);
    return *reinterpret_cast<unsigned*>(&p);
}

// ---------------- fused cnt + mm1 kernel ----------------
// mm1: K-split. 2 threads per (node-quad, out-quad): h=0 -> k[0,64), h=1 -> k[64,128).
// MMN=128 nodes/block, 256 threads, combine via shfl_xor(.,1) at the end.
#define MMN 128                  // nodes per mm1 block
#define KC 16                    // k-chunk (per half: 4 chunks)
#define XSTRIDE (MMN + 4)        // 132
#define XTILE (KC * XSTRIDE)     // 2112
#define HOFF (XTILE + 16)        // 2128: h=1 tile base, +16 floats => +16 banks
#define WCH 260                  // padded W1 chunk stride (4*260 % 32 == 16)
__global__ void __launch_bounds__(256) k_cnt_mm1(const int* __restrict__ dst,
                                                 const float* __restrict__ x,
                                                 const float* __restrict__ W1,
                                                 int ne, int n, int mmBlocks) {
    __shared__ float w1s[8 * WCH];            // 8.3 KB (8 chunks of 16k x 16out)
    __shared__ float xs[2 * HOFF];            // ~17 KB (two half-K tiles)
    int t = threadIdx.x;

    if (blockIdx.x >= mmBlocks) {
        // ---- cnt path: 4 edges per thread ----
        int i = (blockIdx.x - mmBlocks) * blockDim.x + t;
        int base = i * 4;
        if (base + 3 < ne) {
            int4 d = ((const int4*)dst)[i];
            int r0 = atomicAdd(&g_cnt[d.x], 1);
            int r1 = atomicAdd(&g_cnt[d.y], 1);
            int r2 = atomicAdd(&g_cnt[d.z], 1);
            int r3 = atomicAdd(&g_cnt[d.w], 1);
            ((int4*)g_rank)[i] = make_int4(r0, r1, r2, r3);
        } else {
            for (int e = base; e < ne; e++) g_rank[e] = atomicAdd(&g_cnt[dst[e]], 1);
        }
        return;
    }

    // ---- mm1 path ----
    int base = blockIdx.x * MMN;
    int h  = t & 1;                  // K half
    int jg = (t >> 1) & 3;           // output quad
    int nq = t >> 3;                 // node quad (0..31)

    #pragma unroll
    for (int i = t; i < FF * HH; i += 256)
        w1s[(i >> 8) * WCH + (i & 255)] = W1[i];

    float acc[16];
    #pragma unroll
    for (int j = 0; j < 16; j++) acc[j] = 0.0f;

    const float4* xg = (const float4*)x;
    int nloc = t >> 1;               // node within block (0..127)
    int lnode = base + nloc;
    bool ld_ok = lnode < n;
    size_t rowb = (size_t)lnode * 32 + h * 16;   // float4 units: this half's base

    float* xtile = xs + h * HOFF;

    float4 buf[4];
    #pragma unroll
    for (int j = 0; j < 4; j++)
        buf[j] = ld_ok ? xg[rowb + j] : make_float4(0.f, 0.f, 0.f, 0.f);

    #pragma unroll 1
    for (int cc = 0; cc < 4; cc++) {
        if (cc) __syncthreads();
        #pragma unroll
        for (int j = 0; j < 4; j++) {            // transpose into k-major half-tile
            xtile[(j * 4 + 0) * XSTRIDE + nloc] = buf[j].x;
            xtile[(j * 4 + 1) * XSTRIDE + nloc] = buf[j].y;
            xtile[(j * 4 + 2) * XSTRIDE + nloc] = buf[j].z;
            xtile[(j * 4 + 3) * XSTRIDE + nloc] = buf[j].w;
        }
        __syncthreads();                         // also covers w1s on cc==0

        if (cc < 3) {                            // prefetch next chunk of this half
            #pragma unroll
            for (int j = 0; j < 4; j++)
                buf[j] = ld_ok ? xg[rowb + (cc + 1) * 4 + j]
                               : make_float4(0.f, 0.f, 0.f, 0.f);
        }

        int ch = h * 4 + cc;                     // global chunk 0..7
        const float* wbase = &w1s[ch * WCH + jg * 4];
        #pragma unroll
        for (int kk = 0; kk < KC; kk++) {
            float4 xv = *(const float4*)&xtile[kk * XSTRIDE + nq * 4];
            float4 wq = *(const float4*)&wbase[kk * HH];
            acc[0]  += xv.x * wq.x; acc[1]  += xv.x * wq.y;
            acc[2]  += xv.x * wq.z; acc[3]  += xv.x * wq.w;
            acc[4]  += xv.y * wq.x; acc[5]  += xv.y * wq.y;
            acc[6]  += xv.y * wq.z; acc[7]  += xv.y * wq.w;
            acc[8]  += xv.z * wq.x; acc[9]  += xv.z * wq.y;
            acc[10] += xv.z * wq.z; acc[11] += xv.z * wq.w;
            acc[12] += xv.w * wq.x; acc[13] += xv.w * wq.y;
            acc[14] += xv.w * wq.z; acc[15] += xv.w * wq.w;
        }
    }

    // combine the two K halves (partner = t^1: same nq, jg)
    #pragma unroll
    for (int j = 0; j < 16; j++)
        acc[j] += __shfl_xor_sync(0xffffffffu, acc[j], 1);

    if (h == 0) {
        #pragma unroll
        for (int c = 0; c < 4; c++) {
            int node = base + nq * 4 + c;
            if (node < n) {
                uint2 pk;
                pk.x = pack_h2(acc[c*4+0], acc[c*4+1]);
                pk.y = pack_h2(acc[c*4+2], acc[c*4+3]);
                ((uint2*)&g_tmps[(size_t)node * HH])[jg] = pk;  // RAW (dinv in scan1)
            }
        }
    }
}

// ---------------- scan: prefix of g_cnt + dinv + scale g_tmps by dinv ----------------
__global__ void k_scan1(int n) {
    __shared__ int wsum[SB / 32];
    __shared__ int isLast;
    int t = threadIdx.x, b = blockIdx.x;
    if (b == 0 && t < 2 * HH) g_stats[t] = 0.0f;     // zero BN stats for this run
    int i = b * SB + t;
    int v = (i < n) ? g_cnt[i] : 0;
    int x = v;
    #pragma unroll
    for (int off = 1; off < 32; off <<= 1) {
        int y = __shfl_up_sync(0xffffffffu, x, off);
        if ((t & 31) >= off) x += y;
    }
    if ((t & 31) == 31) wsum[t >> 5] = x;
    __syncthreads();
    if (t < SB / 32) {
        int w = wsum[t];
        #pragma unroll
        for (int off = 1; off < SB / 32; off <<= 1) {
            int y = __shfl_up_sync((1u << (SB / 32)) - 1u, w, off);
            if (t >= off) w += y;
        }
        wsum[t] = w;
    }
    __syncthreads();
    int prefix = (t >= 32) ? wsum[(t >> 5) - 1] : 0;
    if (i < n) {
        g_off[i] = prefix + x - v;
        float di = rsqrtf((float)(v + 1));   // +1 self loop
        g_dinv[i] = di;
        // scale this node's raw x@W1 row by dinv (fp16 in place)
        uint4* rowp = (uint4*)&g_tmps[(size_t)i * HH];
        uint4 r0 = rowp[0], r1 = rowp[1];
        float4 a0 = h8_to_f4(make_uint2(r0.x, r0.y));
        float4 a1 = h8_to_f4(make_uint2(r0.z, r0.w));
        float4 a2 = h8_to_f4(make_uint2(r1.x, r1.y));
        float4 a3 = h8_to_f4(make_uint2(r1.z, r1.w));
        uint4 w0, w1;
        w0.x = pack_h2(a0.x * di, a0.y * di); w0.y = pack_h2(a0.z * di, a0.w * di);
        w0.z = pack_h2(a1.x * di, a1.y * di); w0.w = pack_h2(a1.z * di, a1.w * di);
        w1.x = pack_h2(a2.x * di, a2.y * di); w1.y = pack_h2(a2.z * di, a2.w * di);
        w1.z = pack_h2(a3.x * di, a3.y * di); w1.w = pack_h2(a3.z * di, a3.w * di);
        rowp[0] = w0; rowp[1] = w1;
    }
    if (t == SB - 1) g_btot[b] = prefix + x;

    __threadfence();
    __syncthreads();
    if (t == 0) {
        int c = atomicAdd(&g_flag, 1);
        isLast = (c == gridDim.x - 1);
    }
    __syncthreads();
    if (!isLast) return;

    int nb = gridDim.x;                  // <= 256
    if (t < 256) {
        __shared__ int wsum2[8];
        int bv = (t < nb) ? g_btot[t] : 0;
        int bx = bv;
        #pragma unroll
        for (int off = 1; off < 32; off <<= 1) {
            int y = __shfl_up_sync(0xffffffffu, bx, off);
            if ((t & 31) >= off) bx += y;
        }
        if ((t & 31) == 31) wsum2[t >> 5] = bx;
        __syncthreads();
        if (t < 8) {
            int w = wsum2[t];
            #pragma unroll
            for (int off = 1; off < 8; off <<= 1) {
                int y = __shfl_up_sync(0xffu, w, off);
                if (t >= off) w += y;
            }
            wsum2[t] = w;
        }
        __syncthreads();
        int bpre = (t >= 32) ? wsum2[(t >> 5) - 1] : 0;
        if (t < nb) g_bpre[t] = bpre + bx - bv;
        if (t == 0) g_flag = 0;          // self-reset for next replay
    }
}

// ATOMIC-FREE fill: p = off[d] + bpre + rank[e]; csr[p] = src[e]. 4 edges/thread.
__global__ void k_fill(const int* __restrict__ src, const int* __restrict__ dst, int ne) {
    int i = blockIdx.x * blockDim.x + threadIdx.x;
    int base = i * 4;
    if (base + 3 < ne) {
        int4 d = ((const int4*)dst)[i];
        int4 s = ((const int4*)src)[i];
        int4 r = ((const int4*)g_rank)[i];
        int p0 = g_off[d.x] + g_bpre[d.x >> 9] + r.x;
        int p1 = g_off[d.y] + g_bpre[d.y >> 9] + r.y;
        int p2 = g_off[d.z] + g_bpre[d.z >> 9] + r.z;
        int p3 = g_off[d.w] + g_bpre[d.w >> 9] + r.w;
        g_csr[p0] = s.x;
        g_csr[p1] = s.y;
        g_csr[p2] = s.z;
        g_csr[p3] = s.w;
    } else {
        for (int e = base; e < ne; e++) {
            int d = dst[e];
            g_csr[g_off[d] + g_bpre[d >> 9] + g_rank[e]] = src[e];
        }
    }
}

// gather body (R13 form): 8 slots, uint2 per lane, 4 idx + 4 gathers in flight
__device__ __forceinline__ float4 gather_row_sum(const uint2* __restrict__ inp,
                                                 int beg, int cnt, int slot, int c) {
    float4 acc = make_float4(0.f, 0.f, 0.f, 0.f);
    int j = slot;
    for (; j + 24 < cnt; j += 32) {
        int s0 = g_csr[beg + j];
        int s1 = g_csr[beg + j + 8];
        int s2 = g_csr[beg + j + 16];
        int s3 = g_csr[beg + j + 24];
        uint2 r0 = inp[(size_t)s0 * 4 + c];
        uint2 r1 = inp[(size_t)s1 * 4 + c];
        uint2 r2 = inp[(size_t)s2 * 4 + c];
        uint2 r3 = inp[(size_t)s3 * 4 + c];
        acc4(acc, h8_to_f4(r0)); acc4(acc, h8_to_f4(r1));
        acc4(acc, h8_to_f4(r2)); acc4(acc, h8_to_f4(r3));
    }
    if (j + 8 < cnt) {
        int s0 = g_csr[beg + j];
        int s1 = g_csr[beg + j + 8];
        uint2 r0 = inp[(size_t)s0 * 4 + c];
        uint2 r1 = inp[(size_t)s1 * 4 + c];
        acc4(acc, h8_to_f4(r0)); acc4(acc, h8_to_f4(r1));
        j += 16;
    }
    if (j < cnt) {
        int s = g_csr[beg + j];
        acc4(acc, h8_to_f4(inp[(size_t)s * 4 + c]));
    }
    return acc;
}

// conv1 aggregation (fp16 gather, fp32 accum) + relu + bias -> g_h (fp32).
__global__ void __launch_bounds__(256) k_agg1(const float* __restrict__ b1, int n) {
    int t = threadIdx.x;
    int warp = (blockIdx.x * blockDim.x + t) >> 5;
    if (warp >= n) return;

    int lane = t & 31;
    int slot = lane >> 2;
    int c    = lane & 3;
    int beg = g_off[warp] + g_bpre[warp >> 9];
    int cnt = g_cnt[warp];

    const uint2* inp = (const uint2*)g_tmps;
    float4 acc = gather_row_sum(inp, beg, cnt, slot, c);
    if (slot == 0) acc4(acc, h8_to_f4(inp[(size_t)warp * 4 + c]));  // self loop

    #pragma unroll
    for (int off = 4; off < 32; off <<= 1) {
        acc.x += __shfl_xor_sync(0xffffffffu, acc.x, off);
        acc.y += __shfl_xor_sync(0xffffffffu, acc.y, off);
        acc.z += __shfl_xor_sync(0xffffffffu, acc.z, off);
        acc.w += __shfl_xor_sync(0xffffffffu, acc.w, off);
    }
    if (lane < 4) {
        float di = g_dinv[warp];
        float h0 = fmaxf(di * acc.x + __ldg(&b1[4*lane+0]), 0.0f);
        float h1 = fmaxf(di * acc.y + __ldg(&b1[4*lane+1]), 0.0f);
        float h2 = fmaxf(di * acc.z + __ldg(&b1[4*lane+2]), 0.0f);
        float h3 = fmaxf(di * acc.w + __ldg(&b1[4*lane+3]), 0.0f);
        ((float4*)&g_h[(size_t)warp * HH])[lane] = make_float4(h0, h1, h2, h3);
    }
}

// BN statistics over g_h
__global__ void k_stats(int n) {
    __shared__ float sred[2 * HH];
    int t = threadIdx.x;
    if (t < 2 * HH) sred[t] = 0.0f;
    __syncthreads();

    float ls[HH], lq[HH];
    #pragma unroll
    for (int j = 0; j < HH; j++) { ls[j] = 0.0f; lq[j] = 0.0f; }

    for (int node = blockIdx.x * blockDim.x + t; node < n;
         node += gridDim.x * blockDim.x) {
        const float4* hp = (const float4*)&g_h[(size_t)node * HH];
        #pragma unroll
        for (int q = 0; q < 4; q++) {
            float4 a = hp[q];
            ls[4*q+0] += a.x; lq[4*q+0] += a.x * a.x;
            ls[4*q+1] += a.y; lq[4*q+1] += a.y * a.y;
            ls[4*q+2] += a.z; lq[4*q+2] += a.z * a.z;
            ls[4*q+3] += a.w; lq[4*q+3] += a.w * a.w;
        }
    }
    #pragma unroll
    for (int j = 0; j < HH; j++) {
        #pragma unroll
        for (int off = 16; off; off >>= 1) {
            ls[j] += __shfl_xor_sync(0xffffffffu, ls[j], off);
            lq[j] += __shfl_xor_sync(0xffffffffu, lq[j], off);
        }
    }
    if ((t & 31) == 0) {
        #pragma unroll
        for (int j = 0; j < HH; j++) {
            atomicAdd(&sred[j], ls[j]);
            atomicAdd(&sred[HH + j], lq[j]);
        }
    }
    __syncthreads();
    if (t < 2 * HH) atomicAdd(&g_stats[t], sred[t]);
}

// BN finalize + apply + 10 residual hops + dinv pre-scale -> g_h2s (fp16)
__global__ void k_hops(const float* __restrict__ Wl, const float* __restrict__ bl,
                       const float* __restrict__ gamma, const float* __restrict__ beta,
                       float invN, int n) {
    __shared__ float swl[HH * HH];
    __shared__ float sbl[HH], ssc[HH], ssh[HH];
    int t = threadIdx.x;
    if (t < HH * HH) swl[t] = Wl[t];
    if (t < HH) {
        float mean = g_stats[t] * invN;
        float var  = g_stats[HH + t] * invN - mean * mean;
        float sc   = gamma[t] * rsqrtf(var + BN_EPS);
        ssc[t] = sc;
        ssh[t] = beta[t] - mean * sc;
        sbl[t] = bl[t];
    }
    __syncthreads();

    int node = blockIdx.x * blockDim.x + t;
    if (node >= n) return;

    float v[HH];
    const float4* hp = (const float4*)&g_h[(size_t)node * HH];
    #pragma unroll
    for (int q = 0; q < 4; q++) {
        float4 a = hp[q];
        v[4*q+0] = a.x; v[4*q+1] = a.y; v[4*q+2] = a.z; v[4*q+3] = a.w;
    }
    #pragma unroll
    for (int j = 0; j < HH; j++) v[j] = v[j] * ssc[j] + ssh[j];

    #pragma unroll 1
    for (int it = 0; it < 10; it++) {
        float acc[HH];
        #pragma unroll
        for (int j = 0; j < HH; j++) acc[j] = sbl[j];
        #pragma unroll
        for (int k = 0; k < HH; k++) {
            float hk = v[k];
            const float4* wr = (const float4*)&swl[k * HH];
            #pragma unroll
            for (int q = 0; q < 4; q++) {
                float4 w = wr[q];
                acc[4*q+0] += hk * w.x;
                acc[4*q+1] += hk * w.y;
                acc[4*q+2] += hk * w.z;
                acc[4*q+3] += hk * w.w;
            }
        }
        #pragma unroll
        for (int j = 0; j < HH; j++)
            v[j] = ALPHA * fmaxf(acc[j], 0.0f) + (1.0f - ALPHA) * v[j];
    }

    float di = g_dinv[node];
    uint2 pk[2];
    #pragma unroll
    for (int q = 0; q < 2; q++) {
        pk[0].x = pack_h2(v[8*q+0]*di, v[8*q+1]*di);
        pk[0].y = pack_h2(v[8*q+2]*di, v[8*q+3]*di);
        pk[1].x = pack_h2(v[8*q+4]*di, v[8*q+5]*di);
        pk[1].y = pack_h2(v[8*q+6]*di, v[8*q+7]*di);
        ((uint4*)&g_h2s[(size_t)node * HH])[q] =
            make_uint4(pk[0].x, pk[0].y, pk[1].x, pk[1].y);
    }
}

// conv2 aggregation (fp16 gather) fused with W2 GEMM + log_softmax.
__global__ void __launch_bounds__(256) k_agg2_final(const float* __restrict__ W2,
                                                    const float* __restrict__ b2,
                                                    float* __restrict__ out, int n) {
    __shared__ float sw2[HH * CC];
    __shared__ float sb2[CC];
    int t = threadIdx.x;
    for (int i = t; i < HH * CC; i += 256) sw2[i] = W2[i];
    if (t < CC) sb2[t] = b2[t];
    __syncthreads();

    int warp = (blockIdx.x * blockDim.x + t) >> 5;
    if (warp >= n) return;

    int lane = t & 31;
    int slot = lane >> 2;
    int c    = lane & 3;
    int beg = g_off[warp] + g_bpre[warp >> 9];
    int cnt = g_cnt[warp];

    const uint2* inp = (const uint2*)g_h2s;
    float4 acc = gather_row_sum(inp, beg, cnt, slot, c);
    if (slot == 0) acc4(acc, h8_to_f4(inp[(size_t)warp * 4 + c]));  // self loop

    #pragma unroll
    for (int off = 4; off < 32; off <<= 1) {
        acc.x += __shfl_xor_sync(0xffffffffu, acc.x, off);
        acc.y += __shfl_xor_sync(0xffffffffu, acc.y, off);
        acc.z += __shfl_xor_sync(0xffffffffu, acc.z, off);
        acc.w += __shfl_xor_sync(0xffffffffu, acc.w, off);
    }

    float di = g_dinv[warp];
    acc.x *= di; acc.y *= di; acc.z *= di; acc.w *= di;

    float v[HH];
    #pragma unroll
    for (int g = 0; g < 4; g++) {
        v[4*g+0] = __shfl_sync(0xffffffffu, acc.x, g);
        v[4*g+1] = __shfl_sync(0xffffffffu, acc.y, g);
        v[4*g+2] = __shfl_sync(0xffffffffu, acc.z, g);
        v[4*g+3] = __shfl_sync(0xffffffffu, acc.w, g);
    }

    float o0 = sb2[lane];
    float o1 = (lane < CC - 32) ? sb2[32 + lane] : -1e30f;
    #pragma unroll
    for (int k = 0; k < HH; k++) {
        o0 += v[k] * sw2[k * CC + lane];
        if (lane < CC - 32) o1 += v[k] * sw2[k * CC + 32 + lane];
    }

    float m = fmaxf(o0, o1);
    #pragma unroll
    for (int off = 16; off; off >>= 1)
        m = fmaxf(m, __shfl_xor_sync(0xffffffffu, m, off));
    float s = expf(o0 - m) + ((lane < CC - 32) ? expf(o1 - m) : 0.0f);
    #pragma unroll
    for (int off = 16; off; off >>= 1)
        s += __shfl_xor_sync(0xffffffffu, s, off);
    float lse = m + logf(s);

    float* orow = out + (size_t)warp * CC;
    orow[lane] = o0 - lse;
    if (lane < CC - 32) orow[32 + lane] = o1 - lse;
}

// ---------------- launch ----------------
extern "C" void kernel_launch(void* const* d_in, const int* in_sizes, int n_in,
                              void* d_out, int out_size) {
    const float* x     = (const float*)d_in[0];
    const int*   src   = (const int*)d_in[1];
    const int*   dst   = (const int*)d_in[2];
    const float* W1    = (const float*)d_in[3];
    const float* b1    = (const float*)d_in[4];
    const float* gamma = (const float*)d_in[5];
    const float* beta  = (const float*)d_in[6];
    const float* Wl    = (const float*)d_in[7];
    const float* bl    = (const float*)d_in[8];
    const float* W2    = (const float*)d_in[9];
    const float* b2    = (const float*)d_in[10];
    float* out = (float*)d_out;

    int n  = in_sizes[0] / FF;
    int ne = in_sizes[1];
    if (n > NN) n = NN;
    if (ne > EE) ne = EE;

    int nscan = (n + SB - 1) / SB;             // <= 196
    int eb4   = (ne / 4 + 255) / 256 + 1;      // 4 edges per thread (cnt/fill)
    int mmblocks = (n + MMN - 1) / MMN;        // 782 with MMN=128
    int aggblocks = (n * 32 + 255) / 256;      // warp per node
    int nb256 = (n + 255) / 256;

    // zero in-degree counters via memset node
    void* cntPtr = nullptr;
    cudaGetSymbolAddress(&cntPtr, g_cnt);
    cudaMemsetAsync(cntPtr, 0, (size_t)n * sizeof(int));

    // fused: mm1 blocks first (long-running), cnt blocks stream behind
    k_cnt_mm1<<<mmblocks + eb4, 256>>>(dst, x, W1, ne, n, mmblocks);
    k_scan1<<<nscan, SB>>>(n);
    k_fill<<<eb4, 256>>>(src, dst, ne);
    k_agg1<<<aggblocks, 256>>>(b1, n);
    k_stats<<<256, 256>>>(n);
    k_hops<<<nb256, 256>>>(Wl, bl, gamma, beta, 1.0f / (float)n, n);
    k_agg2_final<<<aggblocks, 256>>>(W2, b2, out, n);
}

// round 17
// speedup vs baseline: 1.0584x; 1.0584x over previous
#include <cuda_runtime.h>
#include <cuda_fp16.h>
#include <math.h>

#define NN 100000
#define EE 3200000
#define FF 128
#define HH 16
#define CC 40
#define ALPHA 0.1f
#define BN_EPS 1e-5f
#define SB 512                 // scan block size

// ---------------- scratch (device globals; no allocation) ----------------
__device__ __align__(16) __half g_tmps[NN * HH];  // fp16 x@W1 (raw, then *dinv in scan1)
__device__ __align__(16) __half g_h2s[NN * HH];   // fp16 post-hops hidden * dinv (src-side)
__device__ __align__(16) float g_h[NN * HH];      // fp32 post-relu hidden
__device__ float g_dinv[NN];
__device__ float g_stats[2 * HH];
// CSR machinery
__device__ int g_cnt[NN];          // in-degree (no self loop) -- zeroed by memset node
__device__ int g_off[NN];          // CSR row start (block-LOCAL; add g_bpre[node/SB])
__device__ int g_btot[256];        // scan block totals
__device__ int g_bpre[256];        // scan block prefixes
__device__ int g_flag = 0;         // last-block counter for scan1 (self-resetting)
__device__ int g_rank[EE];         // per-edge rank within its dst row
__device__ int g_csr[EE];          // src indices grouped by dst

// ---------------- helpers ----------------
__device__ __forceinline__ float4 h8_to_f4(uint2 a) {
    __half2 h0 = *reinterpret_cast<__half2*>(&a.x);
    __half2 h1 = *reinterpret_cast<__half2*>(&a.y);
    float2 f0 = __half22float2(h0);
    float2 f1 = __half22float2(h1);
    return make_float4(f0.x, f0.y, f1.x, f1.y);
}
__device__ __forceinline__ void acc4(float4& a, float4 v) {
    a.x += v.x; a.y += v.y; a.z += v.z; a.w += v.w;
}
__device__ __forceinline__ unsigned pack_h2(float a, float b) {
    __half2 p = __floats2half2_rn(a, b);
    return *reinterpret_cast<unsigned*>(&p);
}

// ---------------- fused cnt + mm1 kernel ----------------
#define MMN 256                  // nodes per mm1 block
#define KC 16                    // k-chunk
#define NCH (FF / KC)            // 8 chunks
#define XSTRIDE (MMN + 4)
__global__ void __launch_bounds__(256) k_cnt_mm1(const int* __restrict__ dst,
                                                 const float* __restrict__ x,
                                                 const float* __restrict__ W1,
                                                 int ne, int n, int mmBlocks) {
    __shared__ float w1s[FF * HH];            // 8 KB
    __shared__ float xs_t[KC][XSTRIDE];       // 16.6 KB
    int t = threadIdx.x;

    if (blockIdx.x >= mmBlocks) {
        // ---- cnt path: 4 edges per thread ----
        int i = (blockIdx.x - mmBlocks) * blockDim.x + t;
        int base = i * 4;
        if (base + 3 < ne) {
            int4 d = ((const int4*)dst)[i];
            int r0 = atomicAdd(&g_cnt[d.x], 1);
            int r1 = atomicAdd(&g_cnt[d.y], 1);
            int r2 = atomicAdd(&g_cnt[d.z], 1);
            int r3 = atomicAdd(&g_cnt[d.w], 1);
            ((int4*)g_rank)[i] = make_int4(r0, r1, r2, r3);
        } else {
            for (int e = base; e < ne; e++) g_rank[e] = atomicAdd(&g_cnt[dst[e]], 1);
        }
        return;
    }

    // ---- mm1 path ----
    int base = blockIdx.x * MMN;

    #pragma unroll
    for (int i = t; i < FF * HH; i += 256) w1s[i] = W1[i];

    int nq = t >> 2;                 // node-quad 0..63
    int jg = t & 3;                  // output quad 0..3
    float acc[16];
    #pragma unroll
    for (int j = 0; j < 16; j++) acc[j] = 0.0f;

    const float4* xg = (const float4*)x;
    int node_l = base + t;
    bool ld_ok = node_l < n;
    size_t rowb = (size_t)node_l * (FF / 4);

    float4 buf[KC / 4];
    #pragma unroll
    for (int j = 0; j < KC / 4; j++)
        buf[j] = ld_ok ? xg[rowb + j] : make_float4(0.f, 0.f, 0.f, 0.f);

    #pragma unroll 1
    for (int cc = 0; cc < NCH; cc++) {
        if (cc) __syncthreads();
        #pragma unroll
        for (int j = 0; j < KC / 4; j++) {
            xs_t[j * 4 + 0][t] = buf[j].x;
            xs_t[j * 4 + 1][t] = buf[j].y;
            xs_t[j * 4 + 2][t] = buf[j].z;
            xs_t[j * 4 + 3][t] = buf[j].w;
        }
        __syncthreads();

        if (cc + 1 < NCH) {
            #pragma unroll
            for (int j = 0; j < KC / 4; j++)
                buf[j] = ld_ok ? xg[rowb + (cc + 1) * (KC / 4) + j]
                               : make_float4(0.f, 0.f, 0.f, 0.f);
        }

        const float* wbase = &w1s[cc * KC * HH + jg * 4];
        #pragma unroll
        for (int kk = 0; kk < KC; kk++) {
            float4 xv = *(const float4*)&xs_t[kk][nq * 4];
            float4 wq = *(const float4*)&wbase[kk * HH];
            acc[0]  += xv.x * wq.x; acc[1]  += xv.x * wq.y;
            acc[2]  += xv.x * wq.z; acc[3]  += xv.x * wq.w;
            acc[4]  += xv.y * wq.x; acc[5]  += xv.y * wq.y;
            acc[6]  += xv.y * wq.z; acc[7]  += xv.y * wq.w;
            acc[8]  += xv.z * wq.x; acc[9]  += xv.z * wq.y;
            acc[10] += xv.z * wq.z; acc[11] += xv.z * wq.w;
            acc[12] += xv.w * wq.x; acc[13] += xv.w * wq.y;
            acc[14] += xv.w * wq.z; acc[15] += xv.w * wq.w;
        }
    }

    #pragma unroll
    for (int c = 0; c < 4; c++) {
        int node = base + nq * 4 + c;
        if (node < n) {
            uint2 pk;
            pk.x = pack_h2(acc[c*4+0], acc[c*4+1]);
            pk.y = pack_h2(acc[c*4+2], acc[c*4+3]);
            ((uint2*)&g_tmps[(size_t)node * HH])[jg] = pk;   // RAW (dinv applied in scan1)
        }
    }
}

// ---------------- scan: prefix of g_cnt + dinv + scale g_tmps by dinv ----------------
__global__ void k_scan1(int n) {
    __shared__ int wsum[SB / 32];
    __shared__ int isLast;
    int t = threadIdx.x, b = blockIdx.x;
    if (b == 0 && t < 2 * HH) g_stats[t] = 0.0f;     // zero BN stats for this run
    int i = b * SB + t;
    int v = (i < n) ? g_cnt[i] : 0;
    int x = v;
    #pragma unroll
    for (int off = 1; off < 32; off <<= 1) {
        int y = __shfl_up_sync(0xffffffffu, x, off);
        if ((t & 31) >= off) x += y;
    }
    if ((t & 31) == 31) wsum[t >> 5] = x;
    __syncthreads();
    if (t < SB / 32) {
        int w = wsum[t];
        #pragma unroll
        for (int off = 1; off < SB / 32; off <<= 1) {
            int y = __shfl_up_sync((1u << (SB / 32)) - 1u, w, off);
            if (t >= off) w += y;
        }
        wsum[t] = w;
    }
    __syncthreads();
    int prefix = (t >= 32) ? wsum[(t >> 5) - 1] : 0;
    if (i < n) {
        g_off[i] = prefix + x - v;
        float di = rsqrtf((float)(v + 1));   // +1 self loop
        g_dinv[i] = di;
        // scale this node's raw x@W1 row by dinv (fp16 in place)
        uint4* rowp = (uint4*)&g_tmps[(size_t)i * HH];
        uint4 r0 = rowp[0], r1 = rowp[1];
        float4 a0 = h8_to_f4(make_uint2(r0.x, r0.y));
        float4 a1 = h8_to_f4(make_uint2(r0.z, r0.w));
        float4 a2 = h8_to_f4(make_uint2(r1.x, r1.y));
        float4 a3 = h8_to_f4(make_uint2(r1.z, r1.w));
        uint4 w0, w1;
        w0.x = pack_h2(a0.x * di, a0.y * di); w0.y = pack_h2(a0.z * di, a0.w * di);
        w0.z = pack_h2(a1.x * di, a1.y * di); w0.w = pack_h2(a1.z * di, a1.w * di);
        w1.x = pack_h2(a2.x * di, a2.y * di); w1.y = pack_h2(a2.z * di, a2.w * di);
        w1.z = pack_h2(a3.x * di, a3.y * di); w1.w = pack_h2(a3.z * di, a3.w * di);
        rowp[0] = w0; rowp[1] = w1;
    }
    if (t == SB - 1) g_btot[b] = prefix + x;

    __threadfence();
    __syncthreads();
    if (t == 0) {
        int c = atomicAdd(&g_flag, 1);
        isLast = (c == gridDim.x - 1);
    }
    __syncthreads();
    if (!isLast) return;

    int nb = gridDim.x;                  // <= 256
    if (t < 256) {
        __shared__ int wsum2[8];
        int bv = (t < nb) ? g_btot[t] : 0;
        int bx = bv;
        #pragma unroll
        for (int off = 1; off < 32; off <<= 1) {
            int y = __shfl_up_sync(0xffffffffu, bx, off);
            if ((t & 31) >= off) bx += y;
        }
        if ((t & 31) == 31) wsum2[t >> 5] = bx;
        __syncthreads();
        if (t < 8) {
            int w = wsum2[t];
            #pragma unroll
            for (int off = 1; off < 8; off <<= 1) {
                int y = __shfl_up_sync(0xffu, w, off);
                if (t >= off) w += y;
            }
            wsum2[t] = w;
        }
        __syncthreads();
        int bpre = (t >= 32) ? wsum2[(t >> 5) - 1] : 0;
        if (t < nb) g_bpre[t] = bpre + bx - bv;
        if (t == 0) g_flag = 0;          // self-reset for next replay
    }
}

// ATOMIC-FREE fill: p = off[d] + bpre + rank[e]; csr[p] = src[e]. 4 edges/thread.
__global__ void k_fill(const int* __restrict__ src, const int* __restrict__ dst, int ne) {
    int i = blockIdx.x * blockDim.x + threadIdx.x;
    int base = i * 4;
    if (base + 3 < ne) {
        int4 d = ((const int4*)dst)[i];
        int4 s = ((const int4*)src)[i];
        int4 r = ((const int4*)g_rank)[i];
        int p0 = g_off[d.x] + g_bpre[d.x >> 9] + r.x;
        int p1 = g_off[d.y] + g_bpre[d.y >> 9] + r.y;
        int p2 = g_off[d.z] + g_bpre[d.z >> 9] + r.z;
        int p3 = g_off[d.w] + g_bpre[d.w >> 9] + r.w;
        g_csr[p0] = s.x;
        g_csr[p1] = s.y;
        g_csr[p2] = s.z;
        g_csr[p3] = s.w;
    } else {
        for (int e = base; e < ne; e++) {
            int d = dst[e];
            g_csr[g_off[d] + g_bpre[d >> 9] + g_rank[e]] = src[e];
        }
    }
}

// gather body (R13 form): 8 slots, uint2 per lane, 4 idx + 4 gathers in flight
__device__ __forceinline__ float4 gather_row_sum(const uint2* __restrict__ inp,
                                                 int beg, int cnt, int slot, int c) {
    float4 acc = make_float4(0.f, 0.f, 0.f, 0.f);
    int j = slot;
    for (; j + 24 < cnt; j += 32) {
        int s0 = g_csr[beg + j];
        int s1 = g_csr[beg + j + 8];
        int s2 = g_csr[beg + j + 16];
        int s3 = g_csr[beg + j + 24];
        uint2 r0 = inp[(size_t)s0 * 4 + c];
        uint2 r1 = inp[(size_t)s1 * 4 + c];
        uint2 r2 = inp[(size_t)s2 * 4 + c];
        uint2 r3 = inp[(size_t)s3 * 4 + c];
        acc4(acc, h8_to_f4(r0)); acc4(acc, h8_to_f4(r1));
        acc4(acc, h8_to_f4(r2)); acc4(acc, h8_to_f4(r3));
    }
    if (j + 8 < cnt) {
        int s0 = g_csr[beg + j];
        int s1 = g_csr[beg + j + 8];
        uint2 r0 = inp[(size_t)s0 * 4 + c];
        uint2 r1 = inp[(size_t)s1 * 4 + c];
        acc4(acc, h8_to_f4(r0)); acc4(acc, h8_to_f4(r1));
        j += 16;
    }
    if (j < cnt) {
        int s = g_csr[beg + j];
        acc4(acc, h8_to_f4(inp[(size_t)s * 4 + c]));
    }
    return acc;
}

// conv1 aggregation (fp16 gather, fp32 accum) + relu + bias -> g_h (fp32).
__global__ void __launch_bounds__(256) k_agg1(const float* __restrict__ b1, int n) {
    int t = threadIdx.x;
    int warp = (blockIdx.x * blockDim.x + t) >> 5;
    if (warp >= n) return;

    int lane = t & 31;
    int slot = lane >> 2;
    int c    = lane & 3;
    int beg = g_off[warp] + g_bpre[warp >> 9];
    int cnt = g_cnt[warp];

    const uint2* inp = (const uint2*)g_tmps;
    float4 acc = gather_row_sum(inp, beg, cnt, slot, c);
    if (slot == 0) acc4(acc, h8_to_f4(inp[(size_t)warp * 4 + c]));  // self loop

    #pragma unroll
    for (int off = 4; off < 32; off <<= 1) {
        acc.x += __shfl_xor_sync(0xffffffffu, acc.x, off);
        acc.y += __shfl_xor_sync(0xffffffffu, acc.y, off);
        acc.z += __shfl_xor_sync(0xffffffffu, acc.z, off);
        acc.w += __shfl_xor_sync(0xffffffffu, acc.w, off);
    }
    if (lane < 4) {
        float di = g_dinv[warp];
        float h0 = fmaxf(di * acc.x + __ldg(&b1[4*lane+0]), 0.0f);
        float h1 = fmaxf(di * acc.y + __ldg(&b1[4*lane+1]), 0.0f);
        float h2 = fmaxf(di * acc.z + __ldg(&b1[4*lane+2]), 0.0f);
        float h3 = fmaxf(di * acc.w + __ldg(&b1[4*lane+3]), 0.0f);
        ((float4*)&g_h[(size_t)warp * HH])[lane] = make_float4(h0, h1, h2, h3);
    }
}

// BN statistics over g_h
__global__ void k_stats(int n) {
    __shared__ float sred[2 * HH];
    int t = threadIdx.x;
    if (t < 2 * HH) sred[t] = 0.0f;
    __syncthreads();

    float ls[HH], lq[HH];
    #pragma unroll
    for (int j = 0; j < HH; j++) { ls[j] = 0.0f; lq[j] = 0.0f; }

    for (int node = blockIdx.x * blockDim.x + t; node < n;
         node += gridDim.x * blockDim.x) {
        const float4* hp = (const float4*)&g_h[(size_t)node * HH];
        #pragma unroll
        for (int q = 0; q < 4; q++) {
            float4 a = hp[q];
            ls[4*q+0] += a.x; lq[4*q+0] += a.x * a.x;
            ls[4*q+1] += a.y; lq[4*q+1] += a.y * a.y;
            ls[4*q+2] += a.z; lq[4*q+2] += a.z * a.z;
            ls[4*q+3] += a.w; lq[4*q+3] += a.w * a.w;
        }
    }
    #pragma unroll
    for (int j = 0; j < HH; j++) {
        #pragma unroll
        for (int off = 16; off; off >>= 1) {
            ls[j] += __shfl_xor_sync(0xffffffffu, ls[j], off);
            lq[j] += __shfl_xor_sync(0xffffffffu, lq[j], off);
        }
    }
    if ((t & 31) == 0) {
        #pragma unroll
        for (int j = 0; j < HH; j++) {
            atomicAdd(&sred[j], ls[j]);
            atomicAdd(&sred[HH + j], lq[j]);
        }
    }
    __syncthreads();
    if (t < 2 * HH) atomicAdd(&g_stats[t], sred[t]);
}

// BN finalize + apply + 10 residual hops + dinv pre-scale -> g_h2s (fp16)
__global__ void k_hops(const float* __restrict__ Wl, const float* __restrict__ bl,
                       const float* __restrict__ gamma, const float* __restrict__ beta,
                       float invN, int n) {
    __shared__ float swl[HH * HH];
    __shared__ float sbl[HH], ssc[HH], ssh[HH];
    int t = threadIdx.x;
    if (t < HH * HH) swl[t] = Wl[t];
    if (t < HH) {
        float mean = g_stats[t] * invN;
        float var  = g_stats[HH + t] * invN - mean * mean;
        float sc   = gamma[t] * rsqrtf(var + BN_EPS);
        ssc[t] = sc;
        ssh[t] = beta[t] - mean * sc;
        sbl[t] = bl[t];
    }
    __syncthreads();

    int node = blockIdx.x * blockDim.x + t;
    if (node >= n) return;

    float v[HH];
    const float4* hp = (const float4*)&g_h[(size_t)node * HH];
    #pragma unroll
    for (int q = 0; q < 4; q++) {
        float4 a = hp[q];
        v[4*q+0] = a.x; v[4*q+1] = a.y; v[4*q+2] = a.z; v[4*q+3] = a.w;
    }
    #pragma unroll
    for (int j = 0; j < HH; j++) v[j] = v[j] * ssc[j] + ssh[j];

    #pragma unroll 1
    for (int it = 0; it < 10; it++) {
        float acc[HH];
        #pragma unroll
        for (int j = 0; j < HH; j++) acc[j] = sbl[j];
        #pragma unroll
        for (int k = 0; k < HH; k++) {
            float hk = v[k];
            const float4* wr = (const float4*)&swl[k * HH];
            #pragma unroll
            for (int q = 0; q < 4; q++) {
                float4 w = wr[q];
                acc[4*q+0] += hk * w.x;
                acc[4*q+1] += hk * w.y;
                acc[4*q+2] += hk * w.z;
                acc[4*q+3] += hk * w.w;
            }
        }
        #pragma unroll
        for (int j = 0; j < HH; j++)
            v[j] = ALPHA * fmaxf(acc[j], 0.0f) + (1.0f - ALPHA) * v[j];
    }

    float di = g_dinv[node];
    uint2 pk[2];
    #pragma unroll
    for (int q = 0; q < 2; q++) {
        pk[0].x = pack_h2(v[8*q+0]*di, v[8*q+1]*di);
        pk[0].y = pack_h2(v[8*q+2]*di, v[8*q+3]*di);
        pk[1].x = pack_h2(v[8*q+4]*di, v[8*q+5]*di);
        pk[1].y = pack_h2(v[8*q+6]*di, v[8*q+7]*di);
        ((uint4*)&g_h2s[(size_t)node * HH])[q] =
            make_uint4(pk[0].x, pk[0].y, pk[1].x, pk[1].y);
    }
}

// conv2 aggregation (fp16 gather) fused with W2 GEMM + log_softmax.
__global__ void __launch_bounds__(256) k_agg2_final(const float* __restrict__ W2,
                                                    const float* __restrict__ b2,
                                                    float* __restrict__ out, int n) {
    __shared__ float sw2[HH * CC];
    __shared__ float sb2[CC];
    int t = threadIdx.x;
    for (int i = t; i < HH * CC; i += 256) sw2[i] = W2[i];
    if (t < CC) sb2[t] = b2[t];
    __syncthreads();

    int warp = (blockIdx.x * blockDim.x + t) >> 5;
    if (warp >= n) return;

    int lane = t & 31;
    int slot = lane >> 2;
    int c    = lane & 3;
    int beg = g_off[warp] + g_bpre[warp >> 9];
    int cnt = g_cnt[warp];

    const uint2* inp = (const uint2*)g_h2s;
    float4 acc = gather_row_sum(inp, beg, cnt, slot, c);
    if (slot == 0) acc4(acc, h8_to_f4(inp[(size_t)warp * 4 + c]));  // self loop

    #pragma unroll
    for (int off = 4; off < 32; off <<= 1) {
        acc.x += __shfl_xor_sync(0xffffffffu, acc.x, off);
        acc.y += __shfl_xor_sync(0xffffffffu, acc.y, off);
        acc.z += __shfl_xor_sync(0xffffffffu, acc.z, off);
        acc.w += __shfl_xor_sync(0xffffffffu, acc.w, off);
    }

    float di = g_dinv[warp];
    acc.x *= di; acc.y *= di; acc.z *= di; acc.w *= di;

    float v[HH];
    #pragma unroll
    for (int g = 0; g < 4; g++) {
        v[4*g+0] = __shfl_sync(0xffffffffu, acc.x, g);
        v[4*g+1] = __shfl_sync(0xffffffffu, acc.y, g);
        v[4*g+2] = __shfl_sync(0xffffffffu, acc.z, g);
        v[4*g+3] = __shfl_sync(0xffffffffu, acc.w, g);
    }

    float o0 = sb2[lane];
    float o1 = (lane < CC - 32) ? sb2[32 + lane] : -1e30f;
    #pragma unroll
    for (int k = 0; k < HH; k++) {
        o0 += v[k] * sw2[k * CC + lane];
        if (lane < CC - 32) o1 += v[k] * sw2[k * CC + 32 + lane];
    }

    float m = fmaxf(o0, o1);
    #pragma unroll
    for (int off = 16; off; off >>= 1)
        m = fmaxf(m, __shfl_xor_sync(0xffffffffu, m, off));
    float s = expf(o0 - m) + ((lane < CC - 32) ? expf(o1 - m) : 0.0f);
    #pragma unroll
    for (int off = 16; off; off >>= 1)
        s += __shfl_xor_sync(0xffffffffu, s, off);
    float lse = m + logf(s);

    float* orow = out + (size_t)warp * CC;
    orow[lane] = o0 - lse;
    if (lane < CC - 32) orow[32 + lane] = o1 - lse;
}

// ---------------- launch ----------------
extern "C" void kernel_launch(void* const* d_in, const int* in_sizes, int n_in,
                              void* d_out, int out_size) {
    const float* x     = (const float*)d_in[0];
    const int*   src   = (const int*)d_in[1];
    const int*   dst   = (const int*)d_in[2];
    const float* W1    = (const float*)d_in[3];
    const float* b1    = (const float*)d_in[4];
    const float* gamma = (const float*)d_in[5];
    const float* beta  = (const float*)d_in[6];
    const float* Wl    = (const float*)d_in[7];
    const float* bl    = (const float*)d_in[8];
    const float* W2    = (const float*)d_in[9];
    const float* b2    = (const float*)d_in[10];
    float* out = (float*)d_out;

    int n  = in_sizes[0] / FF;
    int ne = in_sizes[1];
    if (n > NN) n = NN;
    if (ne > EE) ne = EE;

    int nscan = (n + SB - 1) / SB;             // <= 196
    int eb4   = (ne / 4 + 255) / 256 + 1;      // 4 edges per thread (cnt/fill)
    int mmblocks = (n + MMN - 1) / MMN;
    int aggblocks = (n * 32 + 255) / 256;      // warp per node
    int nb256 = (n + 255) / 256;

    // zero in-degree counters via memset node
    void* cntPtr = nullptr;
    cudaGetSymbolAddress(&cntPtr, g_cnt);
    cudaMemsetAsync(cntPtr, 0, (size_t)n * sizeof(int));

    // fused: mm1 blocks first (long-running), cnt blocks stream behind
    k_cnt_mm1<<<mmblocks + eb4, 256>>>(dst, x, W1, ne, n, mmblocks);
    k_scan1<<<nscan, SB>>>(n);
    k_fill<<<eb4, 256>>>(src, dst, ne);
    k_agg1<<<aggblocks, 256>>>(b1, n);
    k_stats<<<256, 256>>>(n);
    k_hops<<<nb256, 256>>>(Wl, bl, gamma, beta, 1.0f / (float)n, n);
    k_agg2_final<<<aggblocks, 256>>>(W2, b2, out, n);
}